// round 15
// baseline (speedup 1.0000x reference)
#include <cuda_runtime.h>
#include <cuda_bf16.h>
#include <cstdint>

#define NN 100000
#define NE 1600000

// ---------------- static scratch (no allocations allowed) ----------------
__device__ __align__(128) float g_h  [NN * 128];
__device__ __align__(128) float g_h2 [NN * 128];
__device__ __align__(128) float g_agg[NN * 128];
__device__ float g_inv[NN];
__device__ int   g_deg[NN];
__device__ float g_wt [7 * 128 * 128];   // transposed weights [k][o]

// ---------------- tiny utility kernels ----------------
__global__ void zero_f_kernel(float* p, int n) {
    int i = blockIdx.x * blockDim.x + threadIdx.x;
    if (i < n) p[i] = 0.f;
}
__global__ void zero_i_kernel(int* p, int n) {
    int i = blockIdx.x * blockDim.x + threadIdx.x;
    if (i < n) p[i] = 0;
}
__global__ void deg_kernel(const int* __restrict__ dst, int* __restrict__ deg) {
    int e = blockIdx.x * blockDim.x + threadIdx.x;
    if (e < NE) atomicAdd(&deg[dst[e]], 1);
}
__global__ void inv_kernel(const int* __restrict__ deg, float* __restrict__ inv) {
    int i = blockIdx.x * blockDim.x + threadIdx.x;
    if (i < NN) {
        int d = deg[i];
        inv[i] = (d > 0) ? (1.f / (float)d) : 0.f;
    }
}
// W[dout][din] row-major -> Wt[din][dout]
__global__ void transpose_kernel(const float* __restrict__ W, float* __restrict__ Wt,
                                 int dout, int din) {
    int idx = blockIdx.x * blockDim.x + threadIdx.x;
    if (idx < dout * din) {
        int o = idx / din;
        int k = idx - o * din;
        Wt[k * dout + o] = W[idx];
    }
}

// ---------------- edge scatter: agg[dst] += h[src], vector red ----------------
template <int F>
__global__ void scatter_kernel(const float* __restrict__ h, const int* __restrict__ ei,
                               float* __restrict__ agg) {
    constexpr int C = F / 4;                 // float4 chunks per row
    int idx = blockIdx.x * blockDim.x + threadIdx.x;
    if (idx >= NE * C) return;
    int e = idx / C;
    int c = idx - e * C;
    int s = ei[e];
    int d = ei[NE + e];
    float4 v = *((const float4*)(h + (size_t)s * F) + c);
    float* p = agg + (size_t)d * F + (size_t)c * 4;
    asm volatile("red.global.add.v4.f32 [%0], {%1, %2, %3, %4};"
                 :: "l"(p), "f"(v.x), "f"(v.y), "f"(v.z), "f"(v.w)
                 : "memory");
}

// ---------------- fused SAGE combine / dense layer ----------------
// out[n] = maybe_relu( (HAS_AGG ? (agg[n]*inv[n]) @ Wl^T : 0) + x[n] @ Wr^T + bias )
// Wlt/Wrt are pre-transposed: Wt[k * D_OUT + o]
template <int D_IN, int D_OUT, bool HAS_AGG, bool RELU>
__global__ __launch_bounds__(256)
void combine_kernel(const float* __restrict__ agg, const float* __restrict__ xin,
                    const float* __restrict__ inv,
                    const float* __restrict__ Wlt, const float* __restrict__ Wrt,
                    const float* __restrict__ bias, float* __restrict__ out) {
    constexpr int KT = 16;            // k-tile
    constexpr int BN = 64;            // nodes per block
    constexpr int TO = D_OUT / 32;    // outputs per thread
    constexpr int TM = 8;             // nodes per thread

    __shared__ float s_x[BN][KT];
    __shared__ float s_a[HAS_AGG ? BN : 1][HAS_AGG ? KT : 1];
    __shared__ float s_wl[HAS_AGG ? KT : 1][HAS_AGG ? D_OUT : 1];
    __shared__ float s_wr[KT][D_OUT];

    const int tid = threadIdx.x;
    const int xo  = tid & 31;         // output lane
    const int yy  = tid >> 5;         // node group (0..7)
    const int node0 = blockIdx.x * BN;

    float acc[TM][TO];
#pragma unroll
    for (int i = 0; i < TM; ++i)
#pragma unroll
        for (int j = 0; j < TO; ++j) acc[i][j] = 0.f;

#pragma unroll 1
    for (int kt = 0; kt < D_IN / KT; ++kt) {
        // load activation tiles
#pragma unroll
        for (int r = 0; r < (BN * KT) / 256; ++r) {
            int id = tid + r * 256;
            int n  = id / KT;
            int k  = id - n * KT;
            int gn = node0 + n;
            float xv = 0.f, av = 0.f;
            if (gn < NN) {
                xv = xin[(size_t)gn * D_IN + kt * KT + k];
                if (HAS_AGG) av = agg[(size_t)gn * D_IN + kt * KT + k] * inv[gn];
            }
            s_x[n][k] = xv;
            if (HAS_AGG) s_a[n][k] = av;
        }
        // load weight tiles (already transposed -> coalesced)
#pragma unroll
        for (int r = 0; r < (KT * D_OUT) / 256; ++r) {
            int id = tid + r * 256;
            int k  = id / D_OUT;
            int o  = id - k * D_OUT;
            if (HAS_AGG) s_wl[k][o] = Wlt[(kt * KT + k) * D_OUT + o];
            s_wr[k][o] = Wrt[(kt * KT + k) * D_OUT + o];
        }
        __syncthreads();

#pragma unroll
        for (int kk = 0; kk < KT; ++kk) {
            float wl[TO], wr[TO];
#pragma unroll
            for (int j = 0; j < TO; ++j) {
                if (HAS_AGG) wl[j] = s_wl[kk][xo + 32 * j];
                wr[j] = s_wr[kk][xo + 32 * j];
            }
#pragma unroll
            for (int i = 0; i < TM; ++i) {
                int n = yy * TM + i;
                float xv = s_x[n][kk];
                float av = HAS_AGG ? s_a[n][kk] : 0.f;
#pragma unroll
                for (int j = 0; j < TO; ++j) {
                    acc[i][j] += xv * wr[j];
                    if (HAS_AGG) acc[i][j] += av * wl[j];
                }
            }
        }
        __syncthreads();
    }

    // epilogue
#pragma unroll
    for (int i = 0; i < TM; ++i) {
        int gn = node0 + yy * TM + i;
        if (gn < NN) {
#pragma unroll
            for (int j = 0; j < TO; ++j) {
                float v = acc[i][j] + bias[xo + 32 * j];
                if (RELU) v = fmaxf(v, 0.f);
                out[(size_t)gn * D_OUT + xo + 32 * j] = v;
            }
        }
    }
}

// ---------------- final classifier: [100k,128] @ Wd2^T + bd2 -> [100k,2] ----------------
__global__ __launch_bounds__(256)
void decoder2_kernel(const float* __restrict__ h, const float* __restrict__ W,
                     const float* __restrict__ b, float* __restrict__ out) {
    __shared__ float w[256];
    int tid = threadIdx.x;
    w[tid] = W[tid];                  // Wd2 is [2][128] = 256 floats
    __syncthreads();
    int n = blockIdx.x * 256 + tid;
    if (n >= NN) return;
    float a0 = b[0], a1 = b[1];
    const float4* hp = (const float4*)(h + (size_t)n * 128);
#pragma unroll
    for (int q = 0; q < 32; ++q) {
        float4 v = hp[q];
        a0 += v.x * w[q * 4 + 0] + v.y * w[q * 4 + 1] + v.z * w[q * 4 + 2] + v.w * w[q * 4 + 3];
        a1 += v.x * w[128 + q * 4 + 0] + v.y * w[128 + q * 4 + 1] +
              v.z * w[128 + q * 4 + 2] + v.w * w[128 + q * 4 + 3];
    }
    out[(size_t)n * 2 + 0] = a0;
    out[(size_t)n * 2 + 1] = a1;
}

// ---------------- launch ----------------
extern "C" void kernel_launch(void* const* d_in, const int* in_sizes, int n_in,
                              void* d_out, int out_size) {
    const float* x   = (const float*)d_in[0];
    const int*   ei  = (const int*)  d_in[1];
    const float* Wl0 = (const float*)d_in[2];
    const float* bl0 = (const float*)d_in[3];
    const float* Wr0 = (const float*)d_in[4];
    const float* Wl1 = (const float*)d_in[5];
    const float* bl1 = (const float*)d_in[6];
    const float* Wr1 = (const float*)d_in[7];
    const float* Wl2 = (const float*)d_in[8];
    const float* bl2 = (const float*)d_in[9];
    const float* Wr2 = (const float*)d_in[10];
    const float* Wd1 = (const float*)d_in[11];
    const float* bd1 = (const float*)d_in[12];
    const float* Wd2 = (const float*)d_in[13];
    const float* bd2 = (const float*)d_in[14];
    float* out = (float*)d_out;

    float *h, *h2, *agg, *inv, *wt;
    int* deg;
    cudaGetSymbolAddress((void**)&h,   g_h);
    cudaGetSymbolAddress((void**)&h2,  g_h2);
    cudaGetSymbolAddress((void**)&agg, g_agg);
    cudaGetSymbolAddress((void**)&inv, g_inv);
    cudaGetSymbolAddress((void**)&deg, g_deg);
    cudaGetSymbolAddress((void**)&wt,  g_wt);

    const float* wt0 = wt + 0 * 16384;  // Wl0^T  [64][128]
    const float* wt1 = wt + 1 * 16384;  // Wr0^T  [64][128]
    const float* wt2 = wt + 2 * 16384;  // Wl1^T  [128][128]
    const float* wt3 = wt + 3 * 16384;  // Wr1^T  [128][128]
    const float* wt4 = wt + 4 * 16384;  // Wl2^T  [128][64]
    const float* wt5 = wt + 5 * 16384;  // Wr2^T  [128][64]
    const float* wt6 = wt + 6 * 16384;  // Wd1^T  [64][128]

    // weight transposes (tiny)
    transpose_kernel<<<(128 * 64 + 255) / 256, 256>>>(Wl0, (float*)wt0, 128, 64);
    transpose_kernel<<<(128 * 64 + 255) / 256, 256>>>(Wr0, (float*)wt1, 128, 64);
    transpose_kernel<<<(128 * 128 + 255) / 256, 256>>>(Wl1, (float*)wt2, 128, 128);
    transpose_kernel<<<(128 * 128 + 255) / 256, 256>>>(Wr1, (float*)wt3, 128, 128);
    transpose_kernel<<<(64 * 128 + 255) / 256, 256>>>(Wl2, (float*)wt4, 64, 128);
    transpose_kernel<<<(64 * 128 + 255) / 256, 256>>>(Wr2, (float*)wt5, 64, 128);
    transpose_kernel<<<(128 * 64 + 255) / 256, 256>>>(Wd1, (float*)wt6, 128, 64);

    // degrees
    zero_i_kernel<<<(NN + 255) / 256, 256>>>(deg, NN);
    deg_kernel<<<(NE + 255) / 256, 256>>>(ei + NE, deg);
    inv_kernel<<<(NN + 255) / 256, 256>>>(deg, inv);

    const int CB = (NN + 63) / 64;   // combine blocks

    // ----- layer 0: 64 -> 128, relu -----
    zero_f_kernel<<<(NN * 64 + 255) / 256, 256>>>(agg, NN * 64);
    scatter_kernel<64><<<(NE * 16 + 255) / 256, 256>>>(x, ei, agg);
    combine_kernel<64, 128, true, true><<<CB, 256>>>(agg, x, inv, wt0, wt1, bl0, h);

    // ----- layer 1: 128 -> 128, relu -----
    zero_f_kernel<<<(NN * 128 + 255) / 256, 256>>>(agg, NN * 128);
    scatter_kernel<128><<<(NE * 32 + 255) / 256, 256>>>(h, ei, agg);
    combine_kernel<128, 128, true, true><<<CB, 256>>>(agg, h, inv, wt2, wt3, bl1, h2);

    // ----- layer 2: 128 -> 64 (no conv relu, but decoder relu follows -> fuse) -----
    zero_f_kernel<<<(NN * 128 + 255) / 256, 256>>>(agg, NN * 128);
    scatter_kernel<128><<<(NE * 32 + 255) / 256, 256>>>(h2, ei, agg);
    combine_kernel<128, 64, true, true><<<CB, 256>>>(agg, h2, inv, wt4, wt5, bl2, h);

    // ----- decoder hidden: 64 -> 128, relu -----
    combine_kernel<64, 128, false, true><<<CB, 256>>>(nullptr, h, nullptr, nullptr, wt6, bd1, h2);

    // ----- decoder output: 128 -> 2 -----
    decoder2_kernel<<<(NN + 255) / 256, 256>>>(h2, Wd2, bd2, out);
}

// round 16
// speedup vs baseline: 1.1072x; 1.1072x over previous
#include <cuda_runtime.h>
#include <cuda_bf16.h>
#include <cstdint>

#define NN 100000
#define NE 1600000

typedef unsigned long long u64;

// ---------------- static scratch (no allocations allowed) ----------------
__device__ __align__(128) float g_h  [NN * 128];
__device__ __align__(128) float g_h2 [NN * 128];
__device__ __align__(128) float g_agg[NN * 128];
__device__ float g_inv[NN];
__device__ int   g_deg[NN];
__device__ float g_wt [7 * 128 * 128];   // transposed weights [k][o], 16384-stride slots

// packed dual-fp32 FMA (Blackwell f32x2 path)
__device__ __forceinline__ u64 fma2(u64 a, u64 b, u64 c) {
    u64 d;
    asm("fma.rn.f32x2 %0, %1, %2, %3;" : "=l"(d) : "l"(a), "l"(b), "l"(c));
    return d;
}

// ---------------- utility kernels ----------------
__global__ void deg_kernel(const int* __restrict__ dst, int* __restrict__ deg) {
    int e = blockIdx.x * blockDim.x + threadIdx.x;
    if (e < NE) atomicAdd(&deg[dst[e]], 1);
}
__global__ void inv_kernel(const int* __restrict__ deg, float* __restrict__ inv) {
    int i = blockIdx.x * blockDim.x + threadIdx.x;
    if (i < NN) {
        int d = deg[i];
        inv[i] = (d > 0) ? (1.f / (float)d) : 0.f;
    }
}

// fused transpose of all 7 weight matrices into g_wt slots
struct WPtrs { const float* s[7]; };
__constant__ int c_dout[7] = {128, 128, 128, 128, 64, 64, 128};
__constant__ int c_din [7] = { 64,  64, 128, 128, 128, 128, 64};
__global__ void transpose_all_kernel(WPtrs p, float* __restrict__ wt) {
    // offsets (elems): cumulative sizes 8192,8192,16384,16384,8192,8192,8192
    int idx = blockIdx.x * blockDim.x + threadIdx.x;   // 0 .. 73727
    int w, base;
    if      (idx < 8192)  { w = 0; base = 0; }
    else if (idx < 16384) { w = 1; base = 8192; }
    else if (idx < 32768) { w = 2; base = 16384; }
    else if (idx < 49152) { w = 3; base = 32768; }
    else if (idx < 57344) { w = 4; base = 49152; }
    else if (idx < 65536) { w = 5; base = 57344; }
    else if (idx < 73728) { w = 6; base = 65536; }
    else return;
    int li = idx - base;
    int din = c_din[w], dout = c_dout[w];
    int o = li / din;
    int k = li - o * din;
    wt[w * 16384 + k * dout + o] = p.s[w][li];
}

// ---------------- edge scatter: agg[dst] += h[src], vector red ----------------
template <int F>
__global__ void scatter_kernel(const float* __restrict__ h, const int* __restrict__ ei,
                               float* __restrict__ agg) {
    constexpr int C = F / 4;
    int idx = blockIdx.x * blockDim.x + threadIdx.x;
    if (idx >= NE * C) return;
    int e = idx / C;
    int c = idx - e * C;
    int s = ei[e];
    int d = ei[NE + e];
    float4 v = *((const float4*)(h + (size_t)s * F) + c);
    float* p = agg + (size_t)d * F + (size_t)c * 4;
    asm volatile("red.global.add.v4.f32 [%0], {%1, %2, %3, %4};"
                 :: "l"(p), "f"(v.x), "f"(v.y), "f"(v.z), "f"(v.w)
                 : "memory");
}

// ---------------- fused SAGE combine / dense layer (f32x2 inner) ----------------
// MODE 0: out = act( x @ Wr^T            [+b] )
// MODE 1: out = act( (agg*inv)@Wl^T + x@Wr^T [+b] )   (agg in input space)
// MODE 2: out = act( agg*inv + x@Wr^T [+b] )          (agg pre-transformed, output space)
template <int D_IN, int D_OUT, int MODE, bool RELU, bool BIASF>
__global__ __launch_bounds__(256)
void combine_kernel(const float* __restrict__ agg, const float* __restrict__ xin,
                    const float* __restrict__ inv,
                    const float* __restrict__ Wlt, const float* __restrict__ Wrt,
                    const float* __restrict__ bias, float* __restrict__ out) {
    constexpr int KT  = 16;
    constexpr int BN  = 64;
    constexpr int TO2 = D_OUT / 64;     // output PAIRS per thread
    constexpr int TM  = 8;
    constexpr bool GA = (MODE == 1);

    __shared__ float2 s_x[BN][KT];                       // duplicated {v,v}
    __shared__ float2 s_a[GA ? BN : 1][GA ? KT : 1];     // duplicated {v,v}
    __shared__ float  s_wl[GA ? KT : 1][GA ? D_OUT : 1];
    __shared__ float  s_wr[KT][D_OUT];

    const int tid = threadIdx.x;
    const int xo  = tid & 31;
    const int yy  = tid >> 5;
    const int node0 = blockIdx.x * BN;

    u64 acc[TM][TO2];
#pragma unroll
    for (int i = 0; i < TM; ++i)
#pragma unroll
        for (int j = 0; j < TO2; ++j) acc[i][j] = 0ull;

#pragma unroll 1
    for (int kt = 0; kt < D_IN / KT; ++kt) {
        // activation tiles (duplicated pairs)
#pragma unroll
        for (int r = 0; r < (BN * KT) / 256; ++r) {
            int id = tid + r * 256;
            int n  = id / KT;
            int k  = id - n * KT;
            int gn = node0 + n;
            float xv = 0.f, av = 0.f;
            if (gn < NN) {
                xv = xin[(size_t)gn * D_IN + kt * KT + k];
                if (GA) av = agg[(size_t)gn * D_IN + kt * KT + k] * inv[gn];
            }
            s_x[n][k] = make_float2(xv, xv);
            if (GA) s_a[n][k] = make_float2(av, av);
        }
        // weight tiles
#pragma unroll
        for (int r = 0; r < (KT * D_OUT) / 256; ++r) {
            int id = tid + r * 256;
            int k  = id / D_OUT;
            int o  = id - k * D_OUT;
            if (GA) s_wl[k][o] = Wlt[(kt * KT + k) * D_OUT + o];
            s_wr[k][o] = Wrt[(kt * KT + k) * D_OUT + o];
        }
        __syncthreads();

#pragma unroll
        for (int kk = 0; kk < KT; ++kk) {
            u64 wl[TO2], wr[TO2];
#pragma unroll
            for (int j = 0; j < TO2; ++j) {
                wr[j] = reinterpret_cast<const u64*>(&s_wr[kk][0])[xo + 32 * j];
                if (GA) wl[j] = reinterpret_cast<const u64*>(&s_wl[kk][0])[xo + 32 * j];
            }
#pragma unroll
            for (int i = 0; i < TM; ++i) {
                int n = yy * TM + i;
                u64 xv = *reinterpret_cast<const u64*>(&s_x[n][kk]);
                u64 av = GA ? *reinterpret_cast<const u64*>(&s_a[n][kk]) : 0ull;
#pragma unroll
                for (int j = 0; j < TO2; ++j) {
                    acc[i][j] = fma2(xv, wr[j], acc[i][j]);
                    if (GA) acc[i][j] = fma2(av, wl[j], acc[i][j]);
                }
            }
        }
        __syncthreads();
    }

    // epilogue
#pragma unroll
    for (int i = 0; i < TM; ++i) {
        int gn = node0 + yy * TM + i;
        if (gn < NN) {
            float iv = (MODE == 2) ? inv[gn] : 0.f;
#pragma unroll
            for (int j = 0; j < TO2; ++j) {
                int o0 = 2 * xo + 64 * j;
                float2 r = *reinterpret_cast<float2*>(&acc[i][j]);
                if (BIASF) { r.x += bias[o0]; r.y += bias[o0 + 1]; }
                if (MODE == 2) {
                    float2 a = *reinterpret_cast<const float2*>(agg + (size_t)gn * D_OUT + o0);
                    r.x += a.x * iv; r.y += a.y * iv;
                }
                if (RELU) { r.x = fmaxf(r.x, 0.f); r.y = fmaxf(r.y, 0.f); }
                *reinterpret_cast<float2*>(out + (size_t)gn * D_OUT + o0) = r;
            }
        }
    }
}

// ---------------- final classifier: [100k,128] @ Wd2^T + bd2 -> [100k,2] ----------------
__global__ __launch_bounds__(256)
void decoder2_kernel(const float* __restrict__ h, const float* __restrict__ W,
                     const float* __restrict__ b, float* __restrict__ out) {
    __shared__ float w[256];
    int tid = threadIdx.x;
    w[tid] = W[tid];
    __syncthreads();
    int n = blockIdx.x * 256 + tid;
    if (n >= NN) return;
    float a0 = b[0], a1 = b[1];
    const float4* hp = (const float4*)(h + (size_t)n * 128);
#pragma unroll
    for (int q = 0; q < 32; ++q) {
        float4 v = hp[q];
        a0 += v.x * w[q * 4 + 0] + v.y * w[q * 4 + 1] + v.z * w[q * 4 + 2] + v.w * w[q * 4 + 3];
        a1 += v.x * w[128 + q * 4 + 0] + v.y * w[128 + q * 4 + 1] +
              v.z * w[128 + q * 4 + 2] + v.w * w[128 + q * 4 + 3];
    }
    out[(size_t)n * 2 + 0] = a0;
    out[(size_t)n * 2 + 1] = a1;
}

// ---------------- launch ----------------
extern "C" void kernel_launch(void* const* d_in, const int* in_sizes, int n_in,
                              void* d_out, int out_size) {
    const float* x   = (const float*)d_in[0];
    const int*   ei  = (const int*)  d_in[1];
    const float* Wl0 = (const float*)d_in[2];
    const float* bl0 = (const float*)d_in[3];
    const float* Wr0 = (const float*)d_in[4];
    const float* Wl1 = (const float*)d_in[5];
    const float* bl1 = (const float*)d_in[6];
    const float* Wr1 = (const float*)d_in[7];
    const float* Wl2 = (const float*)d_in[8];
    const float* bl2 = (const float*)d_in[9];
    const float* Wr2 = (const float*)d_in[10];
    const float* Wd1 = (const float*)d_in[11];
    const float* bd1 = (const float*)d_in[12];
    const float* Wd2 = (const float*)d_in[13];
    const float* bd2 = (const float*)d_in[14];
    float* out = (float*)d_out;

    float *h, *h2, *agg, *inv, *wt;
    int* deg;
    cudaGetSymbolAddress((void**)&h,   g_h);
    cudaGetSymbolAddress((void**)&h2,  g_h2);
    cudaGetSymbolAddress((void**)&agg, g_agg);
    cudaGetSymbolAddress((void**)&inv, g_inv);
    cudaGetSymbolAddress((void**)&deg, g_deg);
    cudaGetSymbolAddress((void**)&wt,  g_wt);

    const float* wt0 = wt + 0 * 16384;  // Wl0^T  [64][128]
    const float* wt1 = wt + 1 * 16384;  // Wr0^T  [64][128]
    const float* wt2 = wt + 2 * 16384;  // Wl1^T  [128][128]
    const float* wt3 = wt + 3 * 16384;  // Wr1^T  [128][128]
    const float* wt4 = wt + 4 * 16384;  // Wl2^T  [128][64]
    const float* wt5 = wt + 5 * 16384;  // Wr2^T  [128][64]
    const float* wt6 = wt + 6 * 16384;  // Wd1^T  [64][128]

    // fused weight transposes
    WPtrs wp;
    wp.s[0] = Wl0; wp.s[1] = Wr0; wp.s[2] = Wl1; wp.s[3] = Wr1;
    wp.s[4] = Wl2; wp.s[5] = Wr2; wp.s[6] = Wd1;
    transpose_all_kernel<<<(73728 + 255) / 256, 256>>>(wp, wt);

    // degrees
    cudaMemsetAsync(deg, 0, NN * sizeof(int));
    deg_kernel<<<(NE + 255) / 256, 256>>>(ei + NE, deg);
    inv_kernel<<<(NN + 255) / 256, 256>>>(deg, inv);

    const int CB = (NN + 63) / 64;

    // ----- layer 0: 64 -> 128, relu (scatter in 64-d input space) -----
    cudaMemsetAsync(agg, 0, (size_t)NN * 64 * sizeof(float));
    scatter_kernel<64><<<(NE * 16 + 255) / 256, 256>>>(x, ei, agg);
    combine_kernel<64, 128, 1, true, true><<<CB, 256>>>(agg, x, inv, wt0, wt1, bl0, h);

    // ----- layer 1: 128 -> 128, relu (scatter in 128-d) -----
    cudaMemsetAsync(agg, 0, (size_t)NN * 128 * sizeof(float));
    scatter_kernel<128><<<(NE * 32 + 255) / 256, 256>>>(h, ei, agg);
    combine_kernel<128, 128, 1, true, true><<<CB, 256>>>(agg, h, inv, wt2, wt3, bl1, h2);

    // ----- layer 2: 128 -> 64 (+decoder relu fused) -----
    // transform-first: y = h2 @ Wl2^T (100k x 64), then scatter y in 64-d
    combine_kernel<128, 64, 0, false, false><<<CB, 256>>>(nullptr, h2, nullptr, nullptr, wt4, nullptr, h);
    cudaMemsetAsync(agg, 0, (size_t)NN * 64 * sizeof(float));
    scatter_kernel<64><<<(NE * 16 + 255) / 256, 256>>>(h, ei, agg);
    combine_kernel<128, 64, 2, true, true><<<CB, 256>>>(agg, h2, inv, nullptr, wt5, bl2, h);

    // ----- decoder hidden: 64 -> 128, relu -----
    combine_kernel<64, 128, 0, true, true><<<CB, 256>>>(nullptr, h, nullptr, nullptr, wt6, bd1, h2);

    // ----- decoder output: 128 -> 2 -----
    decoder2_kernel<<<(NN + 255) / 256, 256>>>(h2, Wd2, bd2, out);
}

// round 17
// speedup vs baseline: 1.5257x; 1.3780x over previous
#include <cuda_runtime.h>
#include <cuda_bf16.h>
#include <cstdint>

#define NN 100000
#define NE 1600000

typedef unsigned long long u64;

// ---------------- static scratch (no allocations allowed) ----------------
__device__ __align__(128) float g_h  [NN * 128];
__device__ __align__(128) float g_h2 [NN * 128];
__device__ __align__(128) float g_agg[NN * 128];
__device__ float g_inv[NN];
__device__ int   g_deg[NN];
__device__ int   g_rowptr[NN];
__device__ int   g_cursor[NN];
__device__ int   g_csr_src[NE];
__device__ int   g_bsum[512];
__device__ float g_wt [7 * 128 * 128];   // transposed weights [k][o]

// packed dual-fp32 FMA (Blackwell f32x2 path)
__device__ __forceinline__ u64 fma2(u64 a, u64 b, u64 c) {
    u64 d;
    asm("fma.rn.f32x2 %0, %1, %2, %3;" : "=l"(d) : "l"(a), "l"(b), "l"(c));
    return d;
}

// ---------------- degree / inv ----------------
__global__ void deg_kernel(const int* __restrict__ dst, int* __restrict__ deg) {
    int e = blockIdx.x * blockDim.x + threadIdx.x;
    if (e < NE) atomicAdd(&deg[dst[e]], 1);
}
__global__ void inv_kernel(const int* __restrict__ deg, float* __restrict__ inv) {
    int i = blockIdx.x * blockDim.x + threadIdx.x;
    if (i < NN) {
        int d = deg[i];
        inv[i] = (d > 0) ? (1.f / (float)d) : 0.f;
    }
}

// ---------------- CSR build: prefix sum over degrees, then fill ----------------
__global__ void block_sum_kernel(const int* __restrict__ deg, int* __restrict__ bsum) {
    __shared__ int s[256];
    int i = blockIdx.x * 256 + threadIdx.x;
    s[threadIdx.x] = (i < NN) ? deg[i] : 0;
    __syncthreads();
    for (int o = 128; o > 0; o >>= 1) {
        if (threadIdx.x < o) s[threadIdx.x] += s[threadIdx.x + o];
        __syncthreads();
    }
    if (threadIdx.x == 0) bsum[blockIdx.x] = s[0];
}
__global__ void scan_bsum_kernel(int* bsum, int nb) {
    if (threadIdx.x == 0 && blockIdx.x == 0) {
        int acc = 0;
        for (int i = 0; i < nb; ++i) { int v = bsum[i]; bsum[i] = acc; acc += v; }
    }
}
__global__ void rowptr_kernel(const int* __restrict__ deg, const int* __restrict__ bsum,
                              int* __restrict__ row_ptr, int* __restrict__ cursor) {
    __shared__ int s[256];
    int tid = threadIdx.x;
    int i = blockIdx.x * 256 + tid;
    int v = (i < NN) ? deg[i] : 0;
    s[tid] = v;
    __syncthreads();
    // Hillis-Steele inclusive scan
    for (int o = 1; o < 256; o <<= 1) {
        int t = (tid >= o) ? s[tid - o] : 0;
        __syncthreads();
        s[tid] += t;
        __syncthreads();
    }
    if (i < NN) {
        int excl = s[tid] - v + bsum[blockIdx.x];
        row_ptr[i] = excl;
        cursor[i]  = excl;
    }
}
__global__ void fill_kernel(const int* __restrict__ ei, int* __restrict__ cursor,
                            int* __restrict__ csr_src) {
    int e = blockIdx.x * blockDim.x + threadIdx.x;
    if (e < NE) {
        int d = ei[NE + e];
        int pos = atomicAdd(&cursor[d], 1);
        csr_src[pos] = ei[e];
    }
}

// ---------------- CSR gather-sum aggregation: agg[n] = inv[n] * sum_{e in(n)} h[src_e]
template <int F>
__global__ __launch_bounds__(256)
void aggregate_kernel(const float* __restrict__ h, const int* __restrict__ row_ptr,
                      const int* __restrict__ deg, const int* __restrict__ csr_src,
                      const float* __restrict__ inv, float* __restrict__ agg) {
    int warp = (blockIdx.x * 256 + threadIdx.x) >> 5;
    int lane = threadIdx.x & 31;
    if (warp >= NN) return;
    int beg = row_ptr[warp];
    int n   = deg[warp];
    float iv = inv[warp];
    if (F == 64) {
        const float2* hp = (const float2*)h;
        float2 a0 = make_float2(0.f, 0.f), a1 = make_float2(0.f, 0.f);
        int t = 0;
        for (; t + 2 <= n; t += 2) {
            int s0 = __ldg(&csr_src[beg + t]);
            int s1 = __ldg(&csr_src[beg + t + 1]);
            float2 v0 = __ldg(&hp[(size_t)s0 * 32 + lane]);
            float2 v1 = __ldg(&hp[(size_t)s1 * 32 + lane]);
            a0.x += v0.x; a0.y += v0.y;
            a1.x += v1.x; a1.y += v1.y;
        }
        if (t < n) {
            int s0 = __ldg(&csr_src[beg + t]);
            float2 v0 = __ldg(&hp[(size_t)s0 * 32 + lane]);
            a0.x += v0.x; a0.y += v0.y;
        }
        a0.x = (a0.x + a1.x) * iv;
        a0.y = (a0.y + a1.y) * iv;
        ((float2*)agg)[(size_t)warp * 32 + lane] = a0;
    } else {
        const float4* hp = (const float4*)h;
        float4 a0 = make_float4(0.f, 0.f, 0.f, 0.f);
        float4 a1 = make_float4(0.f, 0.f, 0.f, 0.f);
        int t = 0;
        for (; t + 2 <= n; t += 2) {
            int s0 = __ldg(&csr_src[beg + t]);
            int s1 = __ldg(&csr_src[beg + t + 1]);
            float4 v0 = __ldg(&hp[(size_t)s0 * 32 + lane]);
            float4 v1 = __ldg(&hp[(size_t)s1 * 32 + lane]);
            a0.x += v0.x; a0.y += v0.y; a0.z += v0.z; a0.w += v0.w;
            a1.x += v1.x; a1.y += v1.y; a1.z += v1.z; a1.w += v1.w;
        }
        if (t < n) {
            int s0 = __ldg(&csr_src[beg + t]);
            float4 v0 = __ldg(&hp[(size_t)s0 * 32 + lane]);
            a0.x += v0.x; a0.y += v0.y; a0.z += v0.z; a0.w += v0.w;
        }
        a0.x = (a0.x + a1.x) * iv; a0.y = (a0.y + a1.y) * iv;
        a0.z = (a0.z + a1.z) * iv; a0.w = (a0.w + a1.w) * iv;
        ((float4*)agg)[(size_t)warp * 32 + lane] = a0;
    }
}

// ---------------- fused weight transpose ----------------
struct WPtrs { const float* s[7]; };
__constant__ int c_dout[7] = {128, 128, 128, 128, 64, 64, 128};
__constant__ int c_din [7] = { 64,  64, 128, 128, 128, 128, 64};
__global__ void transpose_all_kernel(WPtrs p, float* __restrict__ wt) {
    int idx = blockIdx.x * blockDim.x + threadIdx.x;
    int w, base;
    if      (idx < 8192)  { w = 0; base = 0; }
    else if (idx < 16384) { w = 1; base = 8192; }
    else if (idx < 32768) { w = 2; base = 16384; }
    else if (idx < 49152) { w = 3; base = 32768; }
    else if (idx < 57344) { w = 4; base = 49152; }
    else if (idx < 65536) { w = 5; base = 57344; }
    else if (idx < 73728) { w = 6; base = 65536; }
    else return;
    int li = idx - base;
    int din = c_din[w], dout = c_dout[w];
    int o = li / din;
    int k = li - o * din;
    wt[w * 16384 + k * dout + o] = p.s[w][li];
}

// ---------------- fused SAGE combine / dense layer (f32x2 inner) ----------------
// MODE 0: out = act( x @ Wr^T [+b] )
// MODE 1: out = act( agg @ Wl^T + x @ Wr^T [+b] )    (agg pre-scaled by inv)
// MODE 2: out = act( agg + x @ Wr^T [+b] )           (agg in output space, pre-scaled)
template <int D_IN, int D_OUT, int MODE, bool RELU, bool BIASF>
__global__ __launch_bounds__(256)
void combine_kernel(const float* __restrict__ agg, const float* __restrict__ xin,
                    const float* __restrict__ Wlt, const float* __restrict__ Wrt,
                    const float* __restrict__ bias, float* __restrict__ out) {
    constexpr int KT  = 16;
    constexpr int BN  = 64;
    constexpr int TO2 = D_OUT / 64;     // output PAIRS per thread
    constexpr int TM  = 8;
    constexpr bool GA = (MODE == 1);

    __shared__ float2 s_x[BN][KT];                       // duplicated {v,v}
    __shared__ float2 s_a[GA ? BN : 1][GA ? KT : 1];     // duplicated {v,v}
    __shared__ float  s_wl[GA ? KT : 1][GA ? D_OUT : 1];
    __shared__ float  s_wr[KT][D_OUT];

    const int tid = threadIdx.x;
    const int xo  = tid & 31;
    const int yy  = tid >> 5;
    const int node0 = blockIdx.x * BN;

    u64 acc[TM][TO2];
#pragma unroll
    for (int i = 0; i < TM; ++i)
#pragma unroll
        for (int j = 0; j < TO2; ++j) acc[i][j] = 0ull;

#pragma unroll 1
    for (int kt = 0; kt < D_IN / KT; ++kt) {
#pragma unroll
        for (int r = 0; r < (BN * KT) / 256; ++r) {
            int id = tid + r * 256;
            int n  = id / KT;
            int k  = id - n * KT;
            int gn = node0 + n;
            float xv = 0.f, av = 0.f;
            if (gn < NN) {
                xv = xin[(size_t)gn * D_IN + kt * KT + k];
                if (GA) av = agg[(size_t)gn * D_IN + kt * KT + k];
            }
            s_x[n][k] = make_float2(xv, xv);
            if (GA) s_a[n][k] = make_float2(av, av);
        }
#pragma unroll
        for (int r = 0; r < (KT * D_OUT) / 256; ++r) {
            int id = tid + r * 256;
            int k  = id / D_OUT;
            int o  = id - k * D_OUT;
            if (GA) s_wl[k][o] = Wlt[(kt * KT + k) * D_OUT + o];
            s_wr[k][o] = Wrt[(kt * KT + k) * D_OUT + o];
        }
        __syncthreads();

#pragma unroll
        for (int kk = 0; kk < KT; ++kk) {
            u64 wl[TO2], wr[TO2];
#pragma unroll
            for (int j = 0; j < TO2; ++j) {
                wr[j] = reinterpret_cast<const u64*>(&s_wr[kk][0])[xo + 32 * j];
                if (GA) wl[j] = reinterpret_cast<const u64*>(&s_wl[kk][0])[xo + 32 * j];
            }
#pragma unroll
            for (int i = 0; i < TM; ++i) {
                int n = yy * TM + i;
                u64 xv = *reinterpret_cast<const u64*>(&s_x[n][kk]);
                u64 av = GA ? *reinterpret_cast<const u64*>(&s_a[n][kk]) : 0ull;
#pragma unroll
                for (int j = 0; j < TO2; ++j) {
                    acc[i][j] = fma2(xv, wr[j], acc[i][j]);
                    if (GA) acc[i][j] = fma2(av, wl[j], acc[i][j]);
                }
            }
        }
        __syncthreads();
    }

#pragma unroll
    for (int i = 0; i < TM; ++i) {
        int gn = node0 + yy * TM + i;
        if (gn < NN) {
#pragma unroll
            for (int j = 0; j < TO2; ++j) {
                int o0 = 2 * xo + 64 * j;
                float2 r = *reinterpret_cast<float2*>(&acc[i][j]);
                if (BIASF) { r.x += bias[o0]; r.y += bias[o0 + 1]; }
                if (MODE == 2) {
                    float2 a = *reinterpret_cast<const float2*>(agg + (size_t)gn * D_OUT + o0);
                    r.x += a.x; r.y += a.y;
                }
                if (RELU) { r.x = fmaxf(r.x, 0.f); r.y = fmaxf(r.y, 0.f); }
                *reinterpret_cast<float2*>(out + (size_t)gn * D_OUT + o0) = r;
            }
        }
    }
}

// ---------------- final classifier: [100k,128] @ Wd2^T + bd2 -> [100k,2] ----------------
__global__ __launch_bounds__(256)
void decoder2_kernel(const float* __restrict__ h, const float* __restrict__ W,
                     const float* __restrict__ b, float* __restrict__ out) {
    __shared__ float w[256];
    int tid = threadIdx.x;
    w[tid] = W[tid];
    __syncthreads();
    int n = blockIdx.x * 256 + tid;
    if (n >= NN) return;
    float a0 = b[0], a1 = b[1];
    const float4* hp = (const float4*)(h + (size_t)n * 128);
#pragma unroll
    for (int q = 0; q < 32; ++q) {
        float4 v = hp[q];
        a0 += v.x * w[q * 4 + 0] + v.y * w[q * 4 + 1] + v.z * w[q * 4 + 2] + v.w * w[q * 4 + 3];
        a1 += v.x * w[128 + q * 4 + 0] + v.y * w[128 + q * 4 + 1] +
              v.z * w[128 + q * 4 + 2] + v.w * w[128 + q * 4 + 3];
    }
    out[(size_t)n * 2 + 0] = a0;
    out[(size_t)n * 2 + 1] = a1;
}

// ---------------- launch ----------------
extern "C" void kernel_launch(void* const* d_in, const int* in_sizes, int n_in,
                              void* d_out, int out_size) {
    const float* x   = (const float*)d_in[0];
    const int*   ei  = (const int*)  d_in[1];
    const float* Wl0 = (const float*)d_in[2];
    const float* bl0 = (const float*)d_in[3];
    const float* Wr0 = (const float*)d_in[4];
    const float* Wl1 = (const float*)d_in[5];
    const float* bl1 = (const float*)d_in[6];
    const float* Wr1 = (const float*)d_in[7];
    const float* Wl2 = (const float*)d_in[8];
    const float* bl2 = (const float*)d_in[9];
    const float* Wr2 = (const float*)d_in[10];
    const float* Wd1 = (const float*)d_in[11];
    const float* bd1 = (const float*)d_in[12];
    const float* Wd2 = (const float*)d_in[13];
    const float* bd2 = (const float*)d_in[14];
    float* out = (float*)d_out;

    float *h, *h2, *agg, *inv, *wt;
    int *deg, *rowptr, *cursor, *csr, *bsum;
    cudaGetSymbolAddress((void**)&h,      g_h);
    cudaGetSymbolAddress((void**)&h2,     g_h2);
    cudaGetSymbolAddress((void**)&agg,    g_agg);
    cudaGetSymbolAddress((void**)&inv,    g_inv);
    cudaGetSymbolAddress((void**)&deg,    g_deg);
    cudaGetSymbolAddress((void**)&rowptr, g_rowptr);
    cudaGetSymbolAddress((void**)&cursor, g_cursor);
    cudaGetSymbolAddress((void**)&csr,    g_csr_src);
    cudaGetSymbolAddress((void**)&bsum,   g_bsum);
    cudaGetSymbolAddress((void**)&wt,     g_wt);

    const float* wt0 = wt + 0 * 16384;  // Wl0^T
    const float* wt1 = wt + 1 * 16384;  // Wr0^T
    const float* wt2 = wt + 2 * 16384;  // Wl1^T
    const float* wt3 = wt + 3 * 16384;  // Wr1^T
    const float* wt4 = wt + 4 * 16384;  // Wl2^T
    const float* wt5 = wt + 5 * 16384;  // Wr2^T
    const float* wt6 = wt + 6 * 16384;  // Wd1^T

    WPtrs wp;
    wp.s[0] = Wl0; wp.s[1] = Wr0; wp.s[2] = Wl1; wp.s[3] = Wr1;
    wp.s[4] = Wl2; wp.s[5] = Wr2; wp.s[6] = Wd1;
    transpose_all_kernel<<<(73728 + 255) / 256, 256>>>(wp, wt);

    // degrees + CSR build
    const int NB = (NN + 255) / 256;   // 391
    cudaMemsetAsync(deg, 0, NN * sizeof(int));
    deg_kernel<<<(NE + 255) / 256, 256>>>(ei + NE, deg);
    inv_kernel<<<NB, 256>>>(deg, inv);
    block_sum_kernel<<<NB, 256>>>(deg, bsum);
    scan_bsum_kernel<<<1, 32>>>(bsum, NB);
    rowptr_kernel<<<NB, 256>>>(deg, bsum, rowptr, cursor);
    fill_kernel<<<(NE + 255) / 256, 256>>>(ei, cursor, csr);

    const int CB = (NN + 63) / 64;          // combine blocks
    const int AB = (NN * 32 + 255) / 256;   // aggregate blocks (warp per node)

    // ----- layer 0: 64 -> 128, relu -----
    aggregate_kernel<64><<<AB, 256>>>(x, rowptr, deg, csr, inv, agg);
    combine_kernel<64, 128, 1, true, true><<<CB, 256>>>(agg, x, wt0, wt1, bl0, h);

    // ----- layer 1: 128 -> 128, relu -----
    aggregate_kernel<128><<<AB, 256>>>(h, rowptr, deg, csr, inv, agg);
    combine_kernel<128, 128, 1, true, true><<<CB, 256>>>(agg, h, wt2, wt3, bl1, h2);

    // ----- layer 2: 128 -> 64 (+decoder relu fused), transform-first -----
    combine_kernel<128, 64, 0, false, false><<<CB, 256>>>(nullptr, h2, nullptr, wt4, nullptr, h);
    aggregate_kernel<64><<<AB, 256>>>(h, rowptr, deg, csr, inv, agg);
    combine_kernel<128, 64, 2, true, true><<<CB, 256>>>(agg, h2, nullptr, wt5, bl2, h);

    // ----- decoder hidden: 64 -> 128, relu -----
    combine_kernel<64, 128, 0, true, true><<<CB, 256>>>(nullptr, h, nullptr, wt6, bd1, h2);

    // ----- decoder output: 128 -> 2 -----
    decoder2_kernel<<<(NN + 255) / 256, 256>>>(h2, Wd2, bd2, out);
}